// round 10
// baseline (speedup 1.0000x reference)
#include <cuda_runtime.h>
#include <math.h>

#define B_   64
#define C_   256
#define M_   196
#define E_   512
#define CC_  65536
#define KCH  64
#define KCHSZ 1024

// ---------------- scratch (device globals; no allocation) ----------------
__device__ float g_trpart[B_ * 4];        // per-(batch, diag-tile) partial traces of cov
__device__ float g_cov[(size_t)B_ * CC_];  // cov, finally Y3
__device__ float g_Y1 [(size_t)B_ * CC_];
__device__ float g_P2 [(size_t)B_ * CC_];
__device__ float g_R  [(size_t)B_ * CC_];
__device__ float g_W  [(size_t)B_ * CC_];
__device__ float g_part[(size_t)KCH * B_ * E_];
__device__ float g_sqpart[KCH * B_];      // per-(kc,batch) partial sum of squares of Y3

// lower-triangle tile map for 4x4 grid of 64x64 tiles
__constant__ int c_TI[10] = {0,1,1,2,2,2,3,3,3,3};
__constant__ int c_TJ[10] = {0,0,1,0,1,2,0,1,2,3};

// ------- cov = X X^T / M - mu mu^T  (symmetric: 10 lower tiles + mirror) -------
// Row means accumulated in-pass; diag tiles also emit partial traces (no trace pass).
// Ts aliases As/Bs: Ts is only touched after the k-loop (and a __syncthreads),
// where As/Bs are dead.
__global__ __launch_bounds__(256) void cov_kernel(const float* __restrict__ x) {
    __shared__ union SmemCov {
        struct { float As[16][68]; float Bs[16][68]; } db;  // 8704 B live in k-loop
        float Ts[64][65];                                   // 16640 B live after
    } su;
    __shared__ float muA[64];
    __shared__ float muB[64];
    __shared__ float trsh[16];
    int b = blockIdx.y;
    int bi = c_TI[blockIdx.x], bj = c_TJ[blockIdx.x];
    int rowBase = bi * 64, colBase = bj * 64;
    const float* X = x + (size_t)b * C_ * M_;
    int t = threadIdx.x, tx = t & 15, ty = t >> 4;
    int lr = t >> 2, ls = t & 3;
    float acc[4][4] = {};
    float sa = 0.f, sb = 0.f;  // partial row sums (A row lr, B row lr)
    for (int m0 = 0; m0 < M_; m0 += 16) {
        int col = m0 + ls * 4;
        float4 av = make_float4(0.f,0.f,0.f,0.f);
        float4 bv = make_float4(0.f,0.f,0.f,0.f);
        if (col + 3 < M_) {
            av = *(const float4*)(X + (size_t)(rowBase + lr) * M_ + col);
            bv = *(const float4*)(X + (size_t)(colBase + lr) * M_ + col);
        } else if (col < M_) {
            const float* pa = X + (size_t)(rowBase + lr) * M_;
            const float* pb = X + (size_t)(colBase + lr) * M_;
            float ta[4], tb[4];
            #pragma unroll
            for (int j = 0; j < 4; j++) {
                int cc = col + j;
                ta[j] = (cc < M_) ? pa[cc] : 0.f;
                tb[j] = (cc < M_) ? pb[cc] : 0.f;
            }
            av = make_float4(ta[0], ta[1], ta[2], ta[3]);
            bv = make_float4(tb[0], tb[1], tb[2], tb[3]);
        }
        sa += av.x + av.y + av.z + av.w;
        sb += bv.x + bv.y + bv.z + bv.w;
        su.db.As[ls*4+0][lr] = av.x; su.db.As[ls*4+1][lr] = av.y;
        su.db.As[ls*4+2][lr] = av.z; su.db.As[ls*4+3][lr] = av.w;
        su.db.Bs[ls*4+0][lr] = bv.x; su.db.Bs[ls*4+1][lr] = bv.y;
        su.db.Bs[ls*4+2][lr] = bv.z; su.db.Bs[ls*4+3][lr] = bv.w;
        __syncthreads();
        #pragma unroll
        for (int k = 0; k < 16; k++) {
            float4 a = *(const float4*)&su.db.As[k][ty * 4];
            float4 w = *(const float4*)&su.db.Bs[k][tx * 4];
            float aa[4] = {a.x, a.y, a.z, a.w};
            float ww[4] = {w.x, w.y, w.z, w.w};
            #pragma unroll
            for (int i = 0; i < 4; i++)
                #pragma unroll
                for (int j = 0; j < 4; j++) acc[i][j] += aa[i] * ww[j];
        }
        __syncthreads();
    }
    // reduce the 4 ls-lanes (lane-consecutive within a warp) to full row sums
    sa += __shfl_xor_sync(0xffffffffu, sa, 1);
    sa += __shfl_xor_sync(0xffffffffu, sa, 2);
    sb += __shfl_xor_sync(0xffffffffu, sb, 1);
    sb += __shfl_xor_sync(0xffffffffu, sb, 2);
    if (ls == 0) { muA[lr] = sa * (1.0f / M_); muB[lr] = sb * (1.0f / M_); }
    __syncthreads();
    float mui[4], muj[4];
    #pragma unroll
    for (int i = 0; i < 4; i++) mui[i] = muA[ty * 4 + i];
    #pragma unroll
    for (int j = 0; j < 4; j++) muj[j] = muB[tx * 4 + j];
    float* Cp = g_cov + (size_t)b * CC_;
    float ov[4][4];
    #pragma unroll
    for (int i = 0; i < 4; i++) {
        float4 v;
        float* vp = (float*)&v;
        #pragma unroll
        for (int j = 0; j < 4; j++) {
            vp[j] = acc[i][j] * (1.0f / M_) - mui[i] * muj[j];
            ov[i][j] = vp[j];
        }
        *(float4*)(Cp + (size_t)(rowBase + ty * 4 + i) * C_ + colBase + tx * 4) = v;
    }
    if (bi != bj) {
        __syncthreads();   // As/Bs fully dead before Ts overwrite (alias safety)
        #pragma unroll
        for (int i = 0; i < 4; i++)
            #pragma unroll
            for (int j = 0; j < 4; j++) su.Ts[ty * 4 + i][tx * 4 + j] = ov[i][j];
        __syncthreads();
        int mr = t >> 2, cs = (t & 3) * 16;
        float* dst = Cp + (size_t)(colBase + mr) * C_ + rowBase + cs;
        #pragma unroll
        for (int q4 = 0; q4 < 4; q4++) {
            float4 v;
            v.x = su.Ts[cs + q4*4 + 0][mr];
            v.y = su.Ts[cs + q4*4 + 1][mr];
            v.z = su.Ts[cs + q4*4 + 2][mr];
            v.w = su.Ts[cs + q4*4 + 3][mr];
            *(float4*)(dst + q4 * 4) = v;
        }
    } else {
        // diag tile: partial trace (threads tx==ty hold ov[i][i] = diag entries)
        if (tx == ty) trsh[tx] = ov[0][0] + ov[1][1] + ov[2][2] + ov[3][3];
        __syncthreads();
        if (t == 0) {
            float tr = 0.f;
            #pragma unroll
            for (int i = 0; i < 16; i++) tr += trsh[i];
            g_trpart[b * 4 + bi] = tr;
        }
    }
}

// ---- batched symmetric 256^3 GEMM: 10 lower 64x64 tiles + mirror, double-buffered
// MODE 0: C = A@B
// MODE 1: C = 1.5*D - 0.5*s*(A@B)            (P2;  A=cov, B=Y1, D=Y1, s=1/tr)
// MODE 2: C = 1.5*s*D - 0.5*s^2*(A@B)        (Y1;  A=B=D=cov)
// MODE 3: B' = 0.5625*B - 0.0625*A (on load); C = 2.25*I - 2.4375*D + 1.6875*D2 - A@B'
//         (W;  A=R, B=P2, D=P2, D2=R)
// Ts aliases the double buffers (dead after the k-loop's final sync).
template <int MODE>
__global__ __launch_bounds__(256) void gemm_sym_kernel(
    const float* __restrict__ Ag, const float* __restrict__ Bg,
    const float* __restrict__ Dg, const float* __restrict__ D2g,
    float* __restrict__ Cg)
{
    __shared__ union SmemG {
        struct { float As[2][16][68]; float Bs[2][16][68]; } db;  // 17408 B in k-loop
        float Ts[64][65];                                         // 16640 B after
    } su;
    int b = blockIdx.y;
    int bi = c_TI[blockIdx.x], bj = c_TJ[blockIdx.x];
    int rowBase = bi * 64, colBase = bj * 64;
    const float* A  = Ag + (size_t)b * CC_;
    const float* Bp = Bg + (size_t)b * CC_;
    int t = threadIdx.x, tx = t & 15, ty = t >> 4;
    int kr = t >> 4, sg = t & 15;

    // operands symmetric: read row k of A/B directly (coalesced, no transpose)
    const float* aP = A  + (size_t)kr * C_ + rowBase + sg * 4;
    const float* bP = Bp + (size_t)kr * C_ + colBase + sg * 4;
    const float* b2P = A + (size_t)kr * C_ + colBase + sg * 4;  // MODE 3: R at B cols

    float4 na = *(const float4*)aP;
    float4 nb = *(const float4*)bP;
    if (MODE == 3) {
        float4 r4 = *(const float4*)b2P;
        nb.x = 0.5625f * nb.x - 0.0625f * r4.x;
        nb.y = 0.5625f * nb.y - 0.0625f * r4.y;
        nb.z = 0.5625f * nb.z - 0.0625f * r4.z;
        nb.w = 0.5625f * nb.w - 0.0625f * r4.w;
    }
    *(float4*)&su.db.As[0][kr][sg * 4] = na;
    *(float4*)&su.db.Bs[0][kr][sg * 4] = nb;
    __syncthreads();

    float acc[4][4] = {};
    #pragma unroll 2
    for (int kt = 0; kt < 16; kt++) {
        int cur = kt & 1;
        if (kt < 15) {
            size_t off = (size_t)(kt + 1) * 16 * C_;
            na = *(const float4*)(aP + off);
            nb = *(const float4*)(bP + off);
            if (MODE == 3) {
                float4 r4 = *(const float4*)(b2P + off);
                nb.x = 0.5625f * nb.x - 0.0625f * r4.x;
                nb.y = 0.5625f * nb.y - 0.0625f * r4.y;
                nb.z = 0.5625f * nb.z - 0.0625f * r4.z;
                nb.w = 0.5625f * nb.w - 0.0625f * r4.w;
            }
        }
        #pragma unroll
        for (int k = 0; k < 16; k++) {
            float4 a = *(const float4*)&su.db.As[cur][k][ty * 4];
            float4 w = *(const float4*)&su.db.Bs[cur][k][tx * 4];
            float aa[4] = {a.x, a.y, a.z, a.w};
            float ww[4] = {w.x, w.y, w.z, w.w};
            #pragma unroll
            for (int i = 0; i < 4; i++)
                #pragma unroll
                for (int j = 0; j < 4; j++) acc[i][j] += aa[i] * ww[j];
        }
        if (kt < 15) {
            *(float4*)&su.db.As[cur ^ 1][kr][sg * 4] = na;
            *(float4*)&su.db.Bs[cur ^ 1][kr][sg * 4] = nb;
        }
        __syncthreads();
    }

    float s = 0.f;
    if (MODE == 1 || MODE == 2) {
        const float* tp = g_trpart + b * 4;   // deterministic fixed-order sum
        s = 1.0f / (tp[0] + tp[1] + tp[2] + tp[3]);
    }
    float ov[4][4];
    #pragma unroll
    for (int i = 0; i < 4; i++) {
        int row = rowBase + ty * 4 + i;
        size_t idx = (size_t)b * CC_ + (size_t)row * C_ + colBase + tx * 4;
        float4 o;
        float* op = (float*)&o;
        if (MODE == 0) {
            #pragma unroll
            for (int j = 0; j < 4; j++) { op[j] = acc[i][j]; ov[i][j] = op[j]; }
        } else if (MODE == 1) {
            float4 d = *(const float4*)(Dg + idx);
            const float* dp = (const float*)&d;
            #pragma unroll
            for (int j = 0; j < 4; j++) { op[j] = 1.5f * dp[j] - 0.5f * s * acc[i][j]; ov[i][j] = op[j]; }
        } else if (MODE == 2) {
            float4 d = *(const float4*)(Dg + idx);
            const float* dp = (const float*)&d;
            #pragma unroll
            for (int j = 0; j < 4; j++) {
                op[j] = 1.5f * s * dp[j] - 0.5f * s * s * acc[i][j];
                ov[i][j] = op[j];
            }
        } else {  // MODE 3
            float4 p = *(const float4*)(Dg + idx);   // P2 tile
            float4 r = *(const float4*)(D2g + idx);  // R tile
            const float* pp = (const float*)&p;
            const float* rr = (const float*)&r;
            #pragma unroll
            for (int j = 0; j < 4; j++) {
                int col = colBase + tx * 4 + j;
                op[j] = (row == col ? 2.25f : 0.f)
                      - 2.4375f * pp[j] + 1.6875f * rr[j] - acc[i][j];
                ov[i][j] = op[j];
            }
        }
        *(float4*)(Cg + idx) = o;
    }

    if (bi != bj) {
        // mirror tile via smem transpose (As/Bs dead since k-loop's final sync)
        #pragma unroll
        for (int i = 0; i < 4; i++)
            #pragma unroll
            for (int j = 0; j < 4; j++) su.Ts[ty * 4 + i][tx * 4 + j] = ov[i][j];
        __syncthreads();
        int mr = t >> 2, cs = (t & 3) * 16;
        float* dst = Cg + (size_t)b * CC_ + (size_t)(colBase + mr) * C_ + rowBase + cs;
        #pragma unroll
        for (int q4 = 0; q4 < 4; q4++) {
            float4 v;
            v.x = su.Ts[cs + q4*4 + 0][mr];
            v.y = su.Ts[cs + q4*4 + 1][mr];
            v.z = su.Ts[cs + q4*4 + 2][mr];
            v.w = su.Ts[cs + q4*4 + 3][mr];
            *(float4*)(dst + q4 * 4) = v;
        }
    }
}

// ---------------- projection partials, double-buffered: [64,Kc] x [64,Kc]^T ----
// blockIdx.x == 0 blocks also accumulate per-batch partial sums of squares of Y3
// (deterministic split-K Frobenius norm; replaces a separate fnorm pass).
__global__ __launch_bounds__(128) void proj_kernel(const float* __restrict__ W) {
    __shared__ float As[2][16][68];
    __shared__ float Ws[2][16][68];
    int colBase = blockIdx.x * 64;       // E tile
    int kbase = blockIdx.y * KCHSZ;
    int t = threadIdx.x, tx = t & 15, ty = t >> 4;  // ty in 0..7
    int lr0 = t >> 2, ls = t & 3;        // rows 0..31 (row = batch index)
    int lr1 = lr0 + 32;                  // rows 32..63

    const float* aP0 = g_cov + (size_t)lr0 * CC_ + kbase + ls * 4;
    const float* aP1 = g_cov + (size_t)lr1 * CC_ + kbase + ls * 4;
    const float* wP0 = W + (size_t)(colBase + lr0) * CC_ + kbase + ls * 4;
    const float* wP1 = W + (size_t)(colBase + lr1) * CC_ + kbase + ls * 4;

    float sq0 = 0.f, sq1 = 0.f;
    float4 a0 = *(const float4*)aP0;
    float4 a1 = *(const float4*)aP1;
    float4 w0 = *(const float4*)wP0;
    float4 w1 = *(const float4*)wP1;
    if (colBase == 0) {
        sq0 += a0.x*a0.x + a0.y*a0.y + a0.z*a0.z + a0.w*a0.w;
        sq1 += a1.x*a1.x + a1.y*a1.y + a1.z*a1.z + a1.w*a1.w;
    }
    {
        const float* av0 = (const float*)&a0; const float* av1 = (const float*)&a1;
        const float* wv0 = (const float*)&w0; const float* wv1 = (const float*)&w1;
        #pragma unroll
        for (int j = 0; j < 4; j++) {
            As[0][ls*4+j][lr0] = av0[j]; As[0][ls*4+j][lr1] = av1[j];
            Ws[0][ls*4+j][lr0] = wv0[j]; Ws[0][ls*4+j][lr1] = wv1[j];
        }
    }
    __syncthreads();

    float acc[8][4] = {};
    #pragma unroll 2
    for (int kt = 0; kt < KCHSZ / 16; kt++) {
        int cur = kt & 1;
        if (kt < KCHSZ / 16 - 1) {
            int off = (kt + 1) * 16;
            a0 = *(const float4*)(aP0 + off);
            a1 = *(const float4*)(aP1 + off);
            w0 = *(const float4*)(wP0 + off);
            w1 = *(const float4*)(wP1 + off);
            if (colBase == 0) {
                sq0 += a0.x*a0.x + a0.y*a0.y + a0.z*a0.z + a0.w*a0.w;
                sq1 += a1.x*a1.x + a1.y*a1.y + a1.z*a1.z + a1.w*a1.w;
            }
        }
        #pragma unroll
        for (int k = 0; k < 16; k++) {
            float4 av0 = *(const float4*)&As[cur][k][ty * 8];
            float4 av1 = *(const float4*)&As[cur][k][ty * 8 + 4];
            float4 wv = *(const float4*)&Ws[cur][k][tx * 4];
            float aa[8] = {av0.x, av0.y, av0.z, av0.w, av1.x, av1.y, av1.z, av1.w};
            float ww[4] = {wv.x, wv.y, wv.z, wv.w};
            #pragma unroll
            for (int i = 0; i < 8; i++)
                #pragma unroll
                for (int j = 0; j < 4; j++) acc[i][j] += aa[i] * ww[j];
        }
        if (kt < KCHSZ / 16 - 1) {
            const float* av0 = (const float*)&a0; const float* av1 = (const float*)&a1;
            const float* wv0 = (const float*)&w0; const float* wv1 = (const float*)&w1;
            int nxt = cur ^ 1;
            #pragma unroll
            for (int j = 0; j < 4; j++) {
                As[nxt][ls*4+j][lr0] = av0[j]; As[nxt][ls*4+j][lr1] = av1[j];
                Ws[nxt][ls*4+j][lr0] = wv0[j]; Ws[nxt][ls*4+j][lr1] = wv1[j];
            }
        }
        __syncthreads();
    }
    if (colBase == 0) {
        // reduce the 4 ls-lanes (lane-consecutive) to full row slices
        sq0 += __shfl_xor_sync(0xffffffffu, sq0, 1);
        sq0 += __shfl_xor_sync(0xffffffffu, sq0, 2);
        sq1 += __shfl_xor_sync(0xffffffffu, sq1, 1);
        sq1 += __shfl_xor_sync(0xffffffffu, sq1, 2);
        if (ls == 0) {
            g_sqpart[blockIdx.y * B_ + lr0] = sq0;
            g_sqpart[blockIdx.y * B_ + lr1] = sq1;
        }
    }
    float* pp = g_part + (size_t)blockIdx.y * B_ * E_;
    #pragma unroll
    for (int i = 0; i < 8; i++) {
        float4 o = make_float4(acc[i][0], acc[i][1], acc[i][2], acc[i][3]);
        *(float4*)(pp + (size_t)(ty * 8 + i) * E_ + colBase + tx * 4) = o;
    }
}

// ---------------- reduce partials + Frobenius scale + bias + BN + final L2 ----
__global__ void finish_kernel(const float* __restrict__ bproj,
                              const float* __restrict__ gamma,
                              const float* __restrict__ beta,
                              const float* __restrict__ mean,
                              const float* __restrict__ var,
                              float* __restrict__ out)
{
    int b = blockIdx.x, e = threadIdx.x; // 512 threads
    __shared__ float smq[2];
    __shared__ float rn;
    // Frobenius norm of this batch's Y3 from 64 deterministic partials
    float q = (e < KCH) ? g_sqpart[e * B_ + b] : 0.f;
    #pragma unroll
    for (int o = 16; o > 0; o >>= 1) q += __shfl_xor_sync(0xffffffffu, q, o);
    if (e < KCH && (e & 31) == 0) smq[e >> 5] = q;
    __syncthreads();
    if (e == 0) rn = 1.0f / fmaxf(sqrtf(smq[0] + smq[1]), 1e-12f);

    // 4-way split accumulation: breaks the 64-deep serial FADD chain and
    // guarantees >=4 outstanding loads. Fixed order -> deterministic.
    float s0 = 0.f, s1 = 0.f, s2 = 0.f, s3 = 0.f;
    const float* gp = g_part + (size_t)b * E_ + e;
    #pragma unroll 4
    for (int kc = 0; kc < KCH; kc += 4) {
        s0 += gp[(size_t)(kc + 0) * B_ * E_];
        s1 += gp[(size_t)(kc + 1) * B_ * E_];
        s2 += gp[(size_t)(kc + 2) * B_ * E_];
        s3 += gp[(size_t)(kc + 3) * B_ * E_];
    }
    float s = (s0 + s1) + (s2 + s3);
    __syncthreads();
    float v = s * rn + bproj[e];
    v = (v - mean[e]) * rsqrtf(var[e] + 1e-5f) * gamma[e] + beta[e];
    float sq = v * v;
    __shared__ float sm[16];
    __shared__ float total;
    #pragma unroll
    for (int o = 16; o > 0; o >>= 1) sq += __shfl_xor_sync(0xffffffffu, sq, o);
    if ((e & 31) == 0) sm[e >> 5] = sq;
    __syncthreads();
    if (e < 16) {
        float ss = sm[e];
        #pragma unroll
        for (int o = 8; o > 0; o >>= 1) ss += __shfl_xor_sync(0xffffu, ss, o);
        if (e == 0) total = fmaxf(sqrtf(ss), 1e-12f);
    }
    __syncthreads();
    out[(size_t)b * E_ + e] = v / total;
}

// ---------------- launch ----------------
extern "C" void kernel_launch(void* const* d_in, const int* in_sizes, int n_in,
                              void* d_out, int out_size)
{
    const float* feat = (const float*)d_in[0];
    const float* W    = (const float*)d_in[1];
    const float* bp   = (const float*)d_in[2];
    const float* gm   = (const float*)d_in[3];
    const float* bt   = (const float*)d_in[4];
    const float* mn   = (const float*)d_in[5];
    const float* vr   = (const float*)d_in[6];
    float* out = (float*)d_out;

    float *covP, *y1P, *p2P, *rP, *wP;
    cudaGetSymbolAddress((void**)&covP, g_cov);
    cudaGetSymbolAddress((void**)&y1P,  g_Y1);
    cudaGetSymbolAddress((void**)&p2P,  g_P2);
    cudaGetSymbolAddress((void**)&rP,   g_R);
    cudaGetSymbolAddress((void**)&wP,   g_W);

    // stage 1: second-order pooling (symmetric tiles, fused row means + trace partials)
    cov_kernel<<<dim3(10, B_), 256>>>(feat);

    // stage 2: Newton-Schulz collapsed to 5 gemms.
    //   Y1 = 1.5*s*cov - 0.5*s^2*cov^2                 (s = 1/tr, from g_trpart)
    //   P2 = 1.5*Y1 - 0.5*s*cov@Y1
    //   R  = P2^2
    //   W  = 2.25I - 2.4375*P2 + 1.6875*R - R@(0.5625*P2 - 0.0625*R)
    //   Y3 = Y1@W
    dim3 gg(10, B_);
    gemm_sym_kernel<2><<<gg, 256>>>(covP, covP, covP, nullptr, y1P);
    gemm_sym_kernel<1><<<gg, 256>>>(covP, y1P, y1P, nullptr, p2P);
    gemm_sym_kernel<0><<<gg, 256>>>(p2P, p2P, nullptr, nullptr, rP);
    gemm_sym_kernel<3><<<gg, 256>>>(rP, p2P, p2P, rP, wP);
    gemm_sym_kernel<0><<<gg, 256>>>(y1P, wP, nullptr, nullptr, covP);

    // stage 3: projection (+ fused Frobenius partials) + BN + L2
    proj_kernel<<<dim3(E_ / 64, KCH), 128>>>(W);
    finish_kernel<<<B_, 512>>>(bp, gm, bt, mn, vr, out);
}

// round 15
// speedup vs baseline: 1.0991x; 1.0991x over previous
#include <cuda_runtime.h>
#include <math.h>

#define B_   64
#define C_   256
#define M_   196
#define E_   512
#define CC_  65536
#define KCH  64
#define KCHSZ 1024

// ---------------- scratch (device globals; no allocation) ----------------
__device__ float g_trpart[B_ * 4];        // per-(batch, diag-tile) partial traces of cov
__device__ float g_cov[(size_t)B_ * CC_];  // cov, finally Y3
__device__ float g_Y1 [(size_t)B_ * CC_];
__device__ float g_P2 [(size_t)B_ * CC_];
__device__ float g_R  [(size_t)B_ * CC_];
__device__ float g_W  [(size_t)B_ * CC_];
__device__ float g_part[(size_t)KCH * B_ * E_];
__device__ float g_sqpart[KCH * B_];      // per-(kc,batch) partial sum of squares of Y3

// lower-triangle tile map for 4x4 grid of 64x64 tiles
__constant__ int c_TI[10] = {0,1,1,2,2,2,3,3,3,3};
__constant__ int c_TJ[10] = {0,0,1,0,1,2,0,1,2,3};

// ------- cov = X X^T / M - mu mu^T  (symmetric: 10 lower tiles + mirror) -------
// Row means accumulated in-pass; diag tiles also emit partial traces (no trace pass).
__global__ __launch_bounds__(256) void cov_kernel(const float* __restrict__ x) {
    __shared__ union SmemCov {
        struct { float As[16][68]; float Bs[16][68]; } db;
        float Ts[64][65];
    } su;
    __shared__ float muA[64];
    __shared__ float muB[64];
    __shared__ float trsh[16];
    int b = blockIdx.y;
    int bi = c_TI[blockIdx.x], bj = c_TJ[blockIdx.x];
    int rowBase = bi * 64, colBase = bj * 64;
    const float* X = x + (size_t)b * C_ * M_;
    int t = threadIdx.x, tx = t & 15, ty = t >> 4;
    int lr = t >> 2, ls = t & 3;
    float acc[4][4] = {};
    float sa = 0.f, sb = 0.f;  // partial row sums (A row lr, B row lr)
    for (int m0 = 0; m0 < M_; m0 += 16) {
        int col = m0 + ls * 4;
        float4 av = make_float4(0.f,0.f,0.f,0.f);
        float4 bv = make_float4(0.f,0.f,0.f,0.f);
        if (col + 3 < M_) {
            av = *(const float4*)(X + (size_t)(rowBase + lr) * M_ + col);
            bv = *(const float4*)(X + (size_t)(colBase + lr) * M_ + col);
        } else if (col < M_) {
            const float* pa = X + (size_t)(rowBase + lr) * M_;
            const float* pb = X + (size_t)(colBase + lr) * M_;
            float ta[4], tb[4];
            #pragma unroll
            for (int j = 0; j < 4; j++) {
                int cc = col + j;
                ta[j] = (cc < M_) ? pa[cc] : 0.f;
                tb[j] = (cc < M_) ? pb[cc] : 0.f;
            }
            av = make_float4(ta[0], ta[1], ta[2], ta[3]);
            bv = make_float4(tb[0], tb[1], tb[2], tb[3]);
        }
        sa += av.x + av.y + av.z + av.w;
        sb += bv.x + bv.y + bv.z + bv.w;
        su.db.As[ls*4+0][lr] = av.x; su.db.As[ls*4+1][lr] = av.y;
        su.db.As[ls*4+2][lr] = av.z; su.db.As[ls*4+3][lr] = av.w;
        su.db.Bs[ls*4+0][lr] = bv.x; su.db.Bs[ls*4+1][lr] = bv.y;
        su.db.Bs[ls*4+2][lr] = bv.z; su.db.Bs[ls*4+3][lr] = bv.w;
        __syncthreads();
        #pragma unroll
        for (int k = 0; k < 16; k++) {
            float4 a = *(const float4*)&su.db.As[k][ty * 4];
            float4 w = *(const float4*)&su.db.Bs[k][tx * 4];
            float aa[4] = {a.x, a.y, a.z, a.w};
            float ww[4] = {w.x, w.y, w.z, w.w};
            #pragma unroll
            for (int i = 0; i < 4; i++)
                #pragma unroll
                for (int j = 0; j < 4; j++) acc[i][j] += aa[i] * ww[j];
        }
        __syncthreads();
    }
    sa += __shfl_xor_sync(0xffffffffu, sa, 1);
    sa += __shfl_xor_sync(0xffffffffu, sa, 2);
    sb += __shfl_xor_sync(0xffffffffu, sb, 1);
    sb += __shfl_xor_sync(0xffffffffu, sb, 2);
    if (ls == 0) { muA[lr] = sa * (1.0f / M_); muB[lr] = sb * (1.0f / M_); }
    __syncthreads();
    float mui[4], muj[4];
    #pragma unroll
    for (int i = 0; i < 4; i++) mui[i] = muA[ty * 4 + i];
    #pragma unroll
    for (int j = 0; j < 4; j++) muj[j] = muB[tx * 4 + j];
    float* Cp = g_cov + (size_t)b * CC_;
    float ov[4][4];
    #pragma unroll
    for (int i = 0; i < 4; i++) {
        float4 v;
        float* vp = (float*)&v;
        #pragma unroll
        for (int j = 0; j < 4; j++) {
            vp[j] = acc[i][j] * (1.0f / M_) - mui[i] * muj[j];
            ov[i][j] = vp[j];
        }
        *(float4*)(Cp + (size_t)(rowBase + ty * 4 + i) * C_ + colBase + tx * 4) = v;
    }
    if (bi != bj) {
        __syncthreads();   // As/Bs fully dead before Ts overwrite (alias safety)
        #pragma unroll
        for (int i = 0; i < 4; i++)
            #pragma unroll
            for (int j = 0; j < 4; j++) su.Ts[ty * 4 + i][tx * 4 + j] = ov[i][j];
        __syncthreads();
        int mr = t >> 2, cs = (t & 3) * 16;
        float* dst = Cp + (size_t)(colBase + mr) * C_ + rowBase + cs;
        #pragma unroll
        for (int q4 = 0; q4 < 4; q4++) {
            float4 v;
            v.x = su.Ts[cs + q4*4 + 0][mr];
            v.y = su.Ts[cs + q4*4 + 1][mr];
            v.z = su.Ts[cs + q4*4 + 2][mr];
            v.w = su.Ts[cs + q4*4 + 3][mr];
            *(float4*)(dst + q4 * 4) = v;
        }
    } else {
        if (tx == ty) trsh[tx] = ov[0][0] + ov[1][1] + ov[2][2] + ov[3][3];
        __syncthreads();
        if (t == 0) {
            float tr = 0.f;
            #pragma unroll
            for (int i = 0; i < 16; i++) tr += trsh[i];
            g_trpart[b * 4 + bi] = tr;
        }
    }
}

// ---- batched symmetric 256^3 GEMM: 10 lower 64x64 tiles + mirror ----
// 128 threads, 8x4 micro-tile: 1.5 B smem per lane-FMA (below the 128 B/cyc
// crossbar cap at full FMA rate; the 4x4 version was crossbar-bound at L1=66%).
// MODE 0: C = A@B
// MODE 1: C = 1.5*D - 0.5*s*(A@B)            (P2;  A=cov, B=Y1, D=Y1, s=1/tr)
// MODE 2: C = 1.5*s*D - 0.5*s^2*(A@B)        (Y1;  A=B=D=cov)
// MODE 3: B' = 0.5625*B - 0.0625*A (on load); C = 2.25*I - 2.4375*D + 1.6875*D2 - A@B'
template <int MODE>
__global__ __launch_bounds__(128) void gemm_sym_kernel(
    const float* __restrict__ Ag, const float* __restrict__ Bg,
    const float* __restrict__ Dg, const float* __restrict__ D2g,
    float* __restrict__ Cg)
{
    __shared__ union SmemG {
        struct { float As[2][16][68]; float Bs[2][16][68]; } db;  // k-loop
        float Ts[64][65];                                         // mirror (aliased)
    } su;
    int b = blockIdx.y;
    int bi = c_TI[blockIdx.x], bj = c_TJ[blockIdx.x];
    int rowBase = bi * 64, colBase = bj * 64;
    const float* A  = Ag + (size_t)b * CC_;
    const float* Bp = Bg + (size_t)b * CC_;
    int t = threadIdx.x, tx = t & 15, ty = t >> 4;   // ty 0..7
    int kr = t >> 4, sg = t & 15;                    // loader coords

    // operands symmetric: read row k of A/B directly (coalesced, no transpose)
    const float* aP0 = A  + (size_t)kr       * C_ + rowBase + sg * 4;
    const float* aP1 = A  + (size_t)(kr + 8) * C_ + rowBase + sg * 4;
    const float* bP0 = Bp + (size_t)kr       * C_ + colBase + sg * 4;
    const float* bP1 = Bp + (size_t)(kr + 8) * C_ + colBase + sg * 4;
    const float* c2P0 = A + (size_t)kr       * C_ + colBase + sg * 4;  // MODE 3
    const float* c2P1 = A + (size_t)(kr + 8) * C_ + colBase + sg * 4;

    float4 na0 = *(const float4*)aP0;
    float4 na1 = *(const float4*)aP1;
    float4 nb0 = *(const float4*)bP0;
    float4 nb1 = *(const float4*)bP1;
    if (MODE == 3) {
        float4 r0 = *(const float4*)c2P0;
        float4 r1 = *(const float4*)c2P1;
        nb0.x = 0.5625f * nb0.x - 0.0625f * r0.x;
        nb0.y = 0.5625f * nb0.y - 0.0625f * r0.y;
        nb0.z = 0.5625f * nb0.z - 0.0625f * r0.z;
        nb0.w = 0.5625f * nb0.w - 0.0625f * r0.w;
        nb1.x = 0.5625f * nb1.x - 0.0625f * r1.x;
        nb1.y = 0.5625f * nb1.y - 0.0625f * r1.y;
        nb1.z = 0.5625f * nb1.z - 0.0625f * r1.z;
        nb1.w = 0.5625f * nb1.w - 0.0625f * r1.w;
    }
    *(float4*)&su.db.As[0][kr    ][sg * 4] = na0;
    *(float4*)&su.db.As[0][kr + 8][sg * 4] = na1;
    *(float4*)&su.db.Bs[0][kr    ][sg * 4] = nb0;
    *(float4*)&su.db.Bs[0][kr + 8][sg * 4] = nb1;
    __syncthreads();

    float acc[8][4] = {};
    #pragma unroll 2
    for (int kt = 0; kt < 16; kt++) {
        int cur = kt & 1;
        if (kt < 15) {
            size_t off = (size_t)(kt + 1) * 16 * C_;
            na0 = *(const float4*)(aP0 + off);
            na1 = *(const float4*)(aP1 + off);
            nb0 = *(const float4*)(bP0 + off);
            nb1 = *(const float4*)(bP1 + off);
            if (MODE == 3) {
                float4 r0 = *(const float4*)(c2P0 + off);
                float4 r1 = *(const float4*)(c2P1 + off);
                nb0.x = 0.5625f * nb0.x - 0.0625f * r0.x;
                nb0.y = 0.5625f * nb0.y - 0.0625f * r0.y;
                nb0.z = 0.5625f * nb0.z - 0.0625f * r0.z;
                nb0.w = 0.5625f * nb0.w - 0.0625f * r0.w;
                nb1.x = 0.5625f * nb1.x - 0.0625f * r1.x;
                nb1.y = 0.5625f * nb1.y - 0.0625f * r1.y;
                nb1.z = 0.5625f * nb1.z - 0.0625f * r1.z;
                nb1.w = 0.5625f * nb1.w - 0.0625f * r1.w;
            }
        }
        #pragma unroll
        for (int k = 0; k < 16; k++) {
            float4 a0 = *(const float4*)&su.db.As[cur][k][ty * 8];
            float4 a1 = *(const float4*)&su.db.As[cur][k][ty * 8 + 4];
            float4 bv = *(const float4*)&su.db.Bs[cur][k][tx * 4];
            float aa[8] = {a0.x, a0.y, a0.z, a0.w, a1.x, a1.y, a1.z, a1.w};
            float bb[4] = {bv.x, bv.y, bv.z, bv.w};
            #pragma unroll
            for (int i = 0; i < 8; i++)
                #pragma unroll
                for (int j = 0; j < 4; j++) acc[i][j] += aa[i] * bb[j];
        }
        if (kt < 15) {
            *(float4*)&su.db.As[cur ^ 1][kr    ][sg * 4] = na0;
            *(float4*)&su.db.As[cur ^ 1][kr + 8][sg * 4] = na1;
            *(float4*)&su.db.Bs[cur ^ 1][kr    ][sg * 4] = nb0;
            *(float4*)&su.db.Bs[cur ^ 1][kr + 8][sg * 4] = nb1;
        }
        __syncthreads();
    }

    float s = 0.f;
    if (MODE == 1 || MODE == 2) {
        const float* tp = g_trpart + b * 4;   // deterministic fixed-order sum
        s = 1.0f / (tp[0] + tp[1] + tp[2] + tp[3]);
    }
    float ov[8][4];
    #pragma unroll
    for (int i = 0; i < 8; i++) {
        int row = rowBase + ty * 8 + i;
        size_t idx = (size_t)b * CC_ + (size_t)row * C_ + colBase + tx * 4;
        float4 o;
        float* op = (float*)&o;
        if (MODE == 0) {
            #pragma unroll
            for (int j = 0; j < 4; j++) { op[j] = acc[i][j]; ov[i][j] = op[j]; }
        } else if (MODE == 1) {
            float4 d = *(const float4*)(Dg + idx);
            const float* dp = (const float*)&d;
            #pragma unroll
            for (int j = 0; j < 4; j++) { op[j] = 1.5f * dp[j] - 0.5f * s * acc[i][j]; ov[i][j] = op[j]; }
        } else if (MODE == 2) {
            float4 d = *(const float4*)(Dg + idx);
            const float* dp = (const float*)&d;
            #pragma unroll
            for (int j = 0; j < 4; j++) {
                op[j] = 1.5f * s * dp[j] - 0.5f * s * s * acc[i][j];
                ov[i][j] = op[j];
            }
        } else {  // MODE 3
            float4 p = *(const float4*)(Dg + idx);   // P2 tile
            float4 r = *(const float4*)(D2g + idx);  // R tile
            const float* pp = (const float*)&p;
            const float* rr = (const float*)&r;
            #pragma unroll
            for (int j = 0; j < 4; j++) {
                int col = colBase + tx * 4 + j;
                op[j] = (row == col ? 2.25f : 0.f)
                      - 2.4375f * pp[j] + 1.6875f * rr[j] - acc[i][j];
                ov[i][j] = op[j];
            }
        }
        *(float4*)(Cg + idx) = o;
    }

    if (bi != bj) {
        // mirror tile via smem transpose (As/Bs dead since k-loop's final sync)
        #pragma unroll
        for (int i = 0; i < 8; i++)
            #pragma unroll
            for (int j = 0; j < 4; j++) su.Ts[ty * 8 + i][tx * 4 + j] = ov[i][j];
        __syncthreads();
        int mr = t >> 1, cs = (t & 1) * 32;
        float* dst = Cg + (size_t)b * CC_ + (size_t)(colBase + mr) * C_ + rowBase + cs;
        #pragma unroll
        for (int q4 = 0; q4 < 8; q4++) {
            float4 v;
            v.x = su.Ts[cs + q4*4 + 0][mr];
            v.y = su.Ts[cs + q4*4 + 1][mr];
            v.z = su.Ts[cs + q4*4 + 2][mr];
            v.w = su.Ts[cs + q4*4 + 3][mr];
            *(float4*)(dst + q4 * 4) = v;
        }
    }
}

// ---------------- projection partials, double-buffered: [64,Kc] x [64,Kc]^T ----
// blockIdx.x == 0 blocks also accumulate per-batch partial sums of squares of Y3
// (deterministic split-K Frobenius norm; replaces a separate fnorm pass).
__global__ __launch_bounds__(128) void proj_kernel(const float* __restrict__ W) {
    __shared__ float As[2][16][68];
    __shared__ float Ws[2][16][68];
    int colBase = blockIdx.x * 64;       // E tile
    int kbase = blockIdx.y * KCHSZ;
    int t = threadIdx.x, tx = t & 15, ty = t >> 4;  // ty in 0..7
    int lr0 = t >> 2, ls = t & 3;        // rows 0..31 (row = batch index)
    int lr1 = lr0 + 32;                  // rows 32..63

    const float* aP0 = g_cov + (size_t)lr0 * CC_ + kbase + ls * 4;
    const float* aP1 = g_cov + (size_t)lr1 * CC_ + kbase + ls * 4;
    const float* wP0 = W + (size_t)(colBase + lr0) * CC_ + kbase + ls * 4;
    const float* wP1 = W + (size_t)(colBase + lr1) * CC_ + kbase + ls * 4;

    float sq0 = 0.f, sq1 = 0.f;
    float4 a0 = *(const float4*)aP0;
    float4 a1 = *(const float4*)aP1;
    float4 w0 = *(const float4*)wP0;
    float4 w1 = *(const float4*)wP1;
    if (colBase == 0) {
        sq0 += a0.x*a0.x + a0.y*a0.y + a0.z*a0.z + a0.w*a0.w;
        sq1 += a1.x*a1.x + a1.y*a1.y + a1.z*a1.z + a1.w*a1.w;
    }
    {
        const float* av0 = (const float*)&a0; const float* av1 = (const float*)&a1;
        const float* wv0 = (const float*)&w0; const float* wv1 = (const float*)&w1;
        #pragma unroll
        for (int j = 0; j < 4; j++) {
            As[0][ls*4+j][lr0] = av0[j]; As[0][ls*4+j][lr1] = av1[j];
            Ws[0][ls*4+j][lr0] = wv0[j]; Ws[0][ls*4+j][lr1] = wv1[j];
        }
    }
    __syncthreads();

    float acc[8][4] = {};
    #pragma unroll 2
    for (int kt = 0; kt < KCHSZ / 16; kt++) {
        int cur = kt & 1;
        if (kt < KCHSZ / 16 - 1) {
            int off = (kt + 1) * 16;
            a0 = *(const float4*)(aP0 + off);
            a1 = *(const float4*)(aP1 + off);
            w0 = *(const float4*)(wP0 + off);
            w1 = *(const float4*)(wP1 + off);
            if (colBase == 0) {
                sq0 += a0.x*a0.x + a0.y*a0.y + a0.z*a0.z + a0.w*a0.w;
                sq1 += a1.x*a1.x + a1.y*a1.y + a1.z*a1.z + a1.w*a1.w;
            }
        }
        #pragma unroll
        for (int k = 0; k < 16; k++) {
            float4 av0 = *(const float4*)&As[cur][k][ty * 8];
            float4 av1 = *(const float4*)&As[cur][k][ty * 8 + 4];
            float4 wv = *(const float4*)&Ws[cur][k][tx * 4];
            float aa[8] = {av0.x, av0.y, av0.z, av0.w, av1.x, av1.y, av1.z, av1.w};
            float ww[4] = {wv.x, wv.y, wv.z, wv.w};
            #pragma unroll
            for (int i = 0; i < 8; i++)
                #pragma unroll
                for (int j = 0; j < 4; j++) acc[i][j] += aa[i] * ww[j];
        }
        if (kt < KCHSZ / 16 - 1) {
            const float* av0 = (const float*)&a0; const float* av1 = (const float*)&a1;
            const float* wv0 = (const float*)&w0; const float* wv1 = (const float*)&w1;
            int nxt = cur ^ 1;
            #pragma unroll
            for (int j = 0; j < 4; j++) {
                As[nxt][ls*4+j][lr0] = av0[j]; As[nxt][ls*4+j][lr1] = av1[j];
                Ws[nxt][ls*4+j][lr0] = wv0[j]; Ws[nxt][ls*4+j][lr1] = wv1[j];
            }
        }
        __syncthreads();
    }
    if (colBase == 0) {
        sq0 += __shfl_xor_sync(0xffffffffu, sq0, 1);
        sq0 += __shfl_xor_sync(0xffffffffu, sq0, 2);
        sq1 += __shfl_xor_sync(0xffffffffu, sq1, 1);
        sq1 += __shfl_xor_sync(0xffffffffu, sq1, 2);
        if (ls == 0) {
            g_sqpart[blockIdx.y * B_ + lr0] = sq0;
            g_sqpart[blockIdx.y * B_ + lr1] = sq1;
        }
    }
    float* pp = g_part + (size_t)blockIdx.y * B_ * E_;
    #pragma unroll
    for (int i = 0; i < 8; i++) {
        float4 o = make_float4(acc[i][0], acc[i][1], acc[i][2], acc[i][3]);
        *(float4*)(pp + (size_t)(ty * 8 + i) * E_ + colBase + tx * 4) = o;
    }
}

// ---------------- reduce partials + Frobenius scale + bias + BN + final L2 ----
__global__ void finish_kernel(const float* __restrict__ bproj,
                              const float* __restrict__ gamma,
                              const float* __restrict__ beta,
                              const float* __restrict__ mean,
                              const float* __restrict__ var,
                              float* __restrict__ out)
{
    int b = blockIdx.x, e = threadIdx.x; // 512 threads
    __shared__ float smq[2];
    __shared__ float rn;
    float q = (e < KCH) ? g_sqpart[e * B_ + b] : 0.f;
    #pragma unroll
    for (int o = 16; o > 0; o >>= 1) q += __shfl_xor_sync(0xffffffffu, q, o);
    if (e < KCH && (e & 31) == 0) smq[e >> 5] = q;
    __syncthreads();
    if (e == 0) rn = 1.0f / fmaxf(sqrtf(smq[0] + smq[1]), 1e-12f);

    float s0 = 0.f, s1 = 0.f, s2 = 0.f, s3 = 0.f;
    const float* gp = g_part + (size_t)b * E_ + e;
    #pragma unroll 4
    for (int kc = 0; kc < KCH; kc += 4) {
        s0 += gp[(size_t)(kc + 0) * B_ * E_];
        s1 += gp[(size_t)(kc + 1) * B_ * E_];
        s2 += gp[(size_t)(kc + 2) * B_ * E_];
        s3 += gp[(size_t)(kc + 3) * B_ * E_];
    }
    float s = (s0 + s1) + (s2 + s3);
    __syncthreads();
    float v = s * rn + bproj[e];
    v = (v - mean[e]) * rsqrtf(var[e] + 1e-5f) * gamma[e] + beta[e];
    float sq = v * v;
    __shared__ float sm[16];
    __shared__ float total;
    #pragma unroll
    for (int o = 16; o > 0; o >>= 1) sq += __shfl_xor_sync(0xffffffffu, sq, o);
    if ((e & 31) == 0) sm[e >> 5] = sq;
    __syncthreads();
    if (e < 16) {
        float ss = sm[e];
        #pragma unroll
        for (int o = 8; o > 0; o >>= 1) ss += __shfl_xor_sync(0xffffu, ss, o);
        if (e == 0) total = fmaxf(sqrtf(ss), 1e-12f);
    }
    __syncthreads();
    out[(size_t)b * E_ + e] = v / total;
}

// ---------------- launch ----------------
extern "C" void kernel_launch(void* const* d_in, const int* in_sizes, int n_in,
                              void* d_out, int out_size)
{
    const float* feat = (const float*)d_in[0];
    const float* W    = (const float*)d_in[1];
    const float* bp   = (const float*)d_in[2];
    const float* gm   = (const float*)d_in[3];
    const float* bt   = (const float*)d_in[4];
    const float* mn   = (const float*)d_in[5];
    const float* vr   = (const float*)d_in[6];
    float* out = (float*)d_out;

    float *covP, *y1P, *p2P, *rP, *wP;
    cudaGetSymbolAddress((void**)&covP, g_cov);
    cudaGetSymbolAddress((void**)&y1P,  g_Y1);
    cudaGetSymbolAddress((void**)&p2P,  g_P2);
    cudaGetSymbolAddress((void**)&rP,   g_R);
    cudaGetSymbolAddress((void**)&wP,   g_W);

    // stage 1: second-order pooling (symmetric tiles, fused row means + trace partials)
    cov_kernel<<<dim3(10, B_), 256>>>(feat);

    // stage 2: Newton-Schulz collapsed to 5 gemms (8x4 micro-tile, 128 thr).
    //   Y1 = 1.5*s*cov - 0.5*s^2*cov^2                 (s = 1/tr, from g_trpart)
    //   P2 = 1.5*Y1 - 0.5*s*cov@Y1
    //   R  = P2^2
    //   W  = 2.25I - 2.4375*P2 + 1.6875*R - R@(0.5625*P2 - 0.0625*R)
    //   Y3 = Y1@W
    dim3 gg(10, B_);
    gemm_sym_kernel<2><<<gg, 128>>>(covP, covP, covP, nullptr, y1P);
    gemm_sym_kernel<1><<<gg, 128>>>(covP, y1P, y1P, nullptr, p2P);
    gemm_sym_kernel<0><<<gg, 128>>>(p2P, p2P, nullptr, nullptr, rP);
    gemm_sym_kernel<3><<<gg, 128>>>(rP, p2P, p2P, rP, wP);
    gemm_sym_kernel<0><<<gg, 128>>>(y1P, wP, nullptr, nullptr, covP);

    // stage 3: projection (+ fused Frobenius partials) + BN + L2
    proj_kernel<<<dim3(E_ / 64, KCH), 128>>>(W);
    finish_kernel<<<B_, 512>>>(bp, gm, bt, mn, vr, out);
}